// round 1
// baseline (speedup 1.0000x reference)
#include <cuda_runtime.h>

#define NN    50000
#define VOCAB 512
#define D     128
#define D4    32        // float4s per row
#define LN_EPS 1e-5f

// ---------------- device scratch (no allocations allowed) ----------------
__device__ __align__(16) float g_deg [NN];
__device__ __align__(16) float g_dinv[NN];
__device__ __align__(16) float g_x  [NN * D];   // residual input of current layer
__device__ __align__(16) float g_h  [NN * D];   // h = x @ W
__device__ __align__(16) float g_agg[NN * D];   // GCN aggregation accumulator
__device__ __align__(16) float g_G1 [VOCAB * D];// emb @ W1

// ---------------- degree ----------------
__global__ void k_deg_init(int n) {
    int i = blockIdx.x * blockDim.x + threadIdx.x;
    if (i < n) g_deg[i] = 1.0f;   // self-loop weight
}

__global__ void k_deg_acc(const int* __restrict__ col, const float* __restrict__ ew, int E) {
    int e = blockIdx.x * blockDim.x + threadIdx.x;
    if (e < E) atomicAdd(&g_deg[col[e]], ew[e]);
}

__global__ void k_dinv(int n) {
    int i = blockIdx.x * blockDim.x + threadIdx.x;
    if (i < n) g_dinv[i] = rsqrtf(g_deg[i]);   // deg >= 1 always (self loop)
}

// ---------------- G1 = emb @ W1  (512x128 @ 128x128, tiny) ----------------
__global__ void k_small_gemm(const float* __restrict__ A, const float* __restrict__ W) {
    __shared__ float a[D];
    int r = blockIdx.x, t = threadIdx.x;
    a[t] = A[r * D + t];
    __syncthreads();
    float acc = 0.f;
#pragma unroll
    for (int k = 0; k < D; k++) acc = fmaf(a[k], W[k * D + t], acc);
    g_G1[r * D + t] = acc;
}

// ---------------- layer-1 prep: x0 = emb[nid], h1 = G1[nid], agg = dinv^2*h1 + b1 --------
__global__ void k_prep1(const int* __restrict__ nid, const float* __restrict__ emb,
                        const float* __restrict__ b1, int n) {
    int gt = blockIdx.x * blockDim.x + threadIdx.x;
    int node = gt >> 5, lane = gt & 31;
    if (node >= n) return;
    int id = nid[node];
    float4 e = ((const float4*)emb )[id * D4 + lane];
    float4 h = ((const float4*)g_G1)[id * D4 + lane];
    float  di = g_dinv[node];
    float  c  = di * di;
    float4 b = ((const float4*)b1)[lane];
    ((float4*)g_x)[node * D4 + lane] = e;
    ((float4*)g_h)[node * D4 + lane] = h;
    float4 a = make_float4(fmaf(c, h.x, b.x), fmaf(c, h.y, b.y),
                           fmaf(c, h.z, b.z), fmaf(c, h.w, b.w));
    ((float4*)g_agg)[node * D4 + lane] = a;
}

// ---------------- layer-2 prep: agg = dinv^2 * h2 + b2 ----------------
__global__ void k_prep2(const float* __restrict__ b2, int n) {
    int gt = blockIdx.x * blockDim.x + threadIdx.x;
    int node = gt >> 5, lane = gt & 31;
    if (node >= n) return;
    float di = g_dinv[node];
    float c  = di * di;
    float4 h = ((const float4*)g_h)[node * D4 + lane];
    float4 b = ((const float4*)b2)[lane];
    float4 a = make_float4(fmaf(c, h.x, b.x), fmaf(c, h.y, b.y),
                           fmaf(c, h.z, b.z), fmaf(c, h.w, b.w));
    ((float4*)g_agg)[node * D4 + lane] = a;
}

// ---------------- edge scatter: agg[col] += dinv[row]*ew*dinv[col] * h[row] -------------
__global__ void k_edge(const int* __restrict__ rows, const int* __restrict__ cols,
                       const float* __restrict__ ew, int E) {
    int gt = blockIdx.x * blockDim.x + threadIdx.x;
    int e = gt >> 5, lane = gt & 31;
    if (e >= E) return;
    int r = rows[e], c = cols[e];
    float coef = g_dinv[r] * ew[e] * g_dinv[c];
    float4 v = ((const float4*)g_h)[r * D4 + lane];
    v.x *= coef; v.y *= coef; v.z *= coef; v.w *= coef;
#if defined(__CUDA_ARCH__) && (__CUDA_ARCH__ >= 900)
    atomicAdd(((float4*)g_agg) + c * D4 + lane, v);
#else
    float* p = g_agg + c * D + lane * 4;
    atomicAdd(p + 0, v.x); atomicAdd(p + 1, v.y);
    atomicAdd(p + 2, v.z); atomicAdd(p + 3, v.w);
#endif
}

// ---------------- residual + LayerNorm ----------------
__global__ void k_ln(const float* __restrict__ xin, const float* __restrict__ add,
                     const float* __restrict__ gamma, const float* __restrict__ beta,
                     float* __restrict__ out, int n) {
    int gt = blockIdx.x * blockDim.x + threadIdx.x;
    int node = gt >> 5, lane = gt & 31;
    if (node >= n) return;
    float4 a = ((const float4*)xin)[node * D4 + lane];
    float4 b = ((const float4*)add)[node * D4 + lane];
    a.x += b.x; a.y += b.y; a.z += b.z; a.w += b.w;
    float s  = a.x + a.y + a.z + a.w;
    float sq = a.x * a.x + a.y * a.y + a.z * a.z + a.w * a.w;
#pragma unroll
    for (int off = 16; off > 0; off >>= 1) {
        s  += __shfl_xor_sync(0xFFFFFFFFu, s,  off);
        sq += __shfl_xor_sync(0xFFFFFFFFu, sq, off);
    }
    float mu  = s * (1.f / D);
    float var = sq * (1.f / D) - mu * mu;
    float rs  = rsqrtf(var + LN_EPS);
    float4 g  = ((const float4*)gamma)[lane];
    float4 be = ((const float4*)beta )[lane];
    float4 o;
    o.x = (a.x - mu) * rs * g.x + be.x;
    o.y = (a.y - mu) * rs * g.y + be.y;
    o.z = (a.z - mu) * rs * g.z + be.z;
    o.w = (a.w - mu) * rs * g.w + be.w;
    ((float4*)out)[node * D4 + lane] = o;
}

// ---------------- main GEMM: H = X @ W  (n x 128 @ 128 x 128, fp32) ----------------
// BM=64, BN=128 (full), BK=128 (full). 256 threads; micro-tile 4 rows x 8 cols (4+4 split).
#define GEMM_SMEM (64 * 132 * 4 + 128 * 128 * 4)   // Xs padded + Ws

__global__ void k_gemm(const float* __restrict__ X, const float* __restrict__ W,
                       float* __restrict__ H, int n) {
    extern __shared__ float smem[];
    float* Xs = smem;             // [64][132] padded
    float* Ws = smem + 64 * 132;  // [128][128]

    int t  = threadIdx.x;
    int m0 = blockIdx.x * 64;

    // load W (16384 floats -> 4096 float4 / 256 threads = 16 each)
    const float4* W4  = (const float4*)W;
    float4*       Ws4 = (float4*)Ws;
#pragma unroll
    for (int i = 0; i < 16; i++) Ws4[t + i * 256] = W4[t + i * 256];

    // load X tile (64 rows x 32 float4 = 2048 float4 / 256 threads = 8 each)
#pragma unroll
    for (int i = 0; i < 8; i++) {
        int idx = t + i * 256;
        int r = idx >> 5, kc = idx & 31;
        float4 v = make_float4(0.f, 0.f, 0.f, 0.f);
        if (m0 + r < n) v = ((const float4*)X)[(m0 + r) * D4 + kc];
        *(float4*)&Xs[r * 132 + kc * 4] = v;
    }
    __syncthreads();

    int cg = t & 15;    // column group: cols cg*4 and 64+cg*4
    int rg = t >> 4;    // row group:    rows rg*4 .. rg*4+3

    float acc[4][8];
#pragma unroll
    for (int i = 0; i < 4; i++)
#pragma unroll
        for (int j = 0; j < 8; j++) acc[i][j] = 0.f;

#pragma unroll 8
    for (int k = 0; k < D; k++) {
        float a0 = Xs[(rg * 4 + 0) * 132 + k];
        float a1 = Xs[(rg * 4 + 1) * 132 + k];
        float a2 = Xs[(rg * 4 + 2) * 132 + k];
        float a3 = Xs[(rg * 4 + 3) * 132 + k];
        float4 w0 = *(const float4*)&Ws[k * D + cg * 4];
        float4 w1 = *(const float4*)&Ws[k * D + 64 + cg * 4];
        acc[0][0] = fmaf(a0, w0.x, acc[0][0]); acc[0][1] = fmaf(a0, w0.y, acc[0][1]);
        acc[0][2] = fmaf(a0, w0.z, acc[0][2]); acc[0][3] = fmaf(a0, w0.w, acc[0][3]);
        acc[0][4] = fmaf(a0, w1.x, acc[0][4]); acc[0][5] = fmaf(a0, w1.y, acc[0][5]);
        acc[0][6] = fmaf(a0, w1.z, acc[0][6]); acc[0][7] = fmaf(a0, w1.w, acc[0][7]);
        acc[1][0] = fmaf(a1, w0.x, acc[1][0]); acc[1][1] = fmaf(a1, w0.y, acc[1][1]);
        acc[1][2] = fmaf(a1, w0.z, acc[1][2]); acc[1][3] = fmaf(a1, w0.w, acc[1][3]);
        acc[1][4] = fmaf(a1, w1.x, acc[1][4]); acc[1][5] = fmaf(a1, w1.y, acc[1][5]);
        acc[1][6] = fmaf(a1, w1.z, acc[1][6]); acc[1][7] = fmaf(a1, w1.w, acc[1][7]);
        acc[2][0] = fmaf(a2, w0.x, acc[2][0]); acc[2][1] = fmaf(a2, w0.y, acc[2][1]);
        acc[2][2] = fmaf(a2, w0.z, acc[2][2]); acc[2][3] = fmaf(a2, w0.w, acc[2][3]);
        acc[2][4] = fmaf(a2, w1.x, acc[2][4]); acc[2][5] = fmaf(a2, w1.y, acc[2][5]);
        acc[2][6] = fmaf(a2, w1.z, acc[2][6]); acc[2][7] = fmaf(a2, w1.w, acc[2][7]);
        acc[3][0] = fmaf(a3, w0.x, acc[3][0]); acc[3][1] = fmaf(a3, w0.y, acc[3][1]);
        acc[3][2] = fmaf(a3, w0.z, acc[3][2]); acc[3][3] = fmaf(a3, w0.w, acc[3][3]);
        acc[3][4] = fmaf(a3, w1.x, acc[3][4]); acc[3][5] = fmaf(a3, w1.y, acc[3][5]);
        acc[3][6] = fmaf(a3, w1.z, acc[3][6]); acc[3][7] = fmaf(a3, w1.w, acc[3][7]);
    }

#pragma unroll
    for (int i = 0; i < 4; i++) {
        int row = m0 + rg * 4 + i;
        if (row < n) {
            float4 o0 = make_float4(acc[i][0], acc[i][1], acc[i][2], acc[i][3]);
            float4 o1 = make_float4(acc[i][4], acc[i][5], acc[i][6], acc[i][7]);
            ((float4*)H)[row * D4 + cg]      = o0;
            ((float4*)H)[row * D4 + 16 + cg] = o1;
        }
    }
}

// ---------------- host launch ----------------
extern "C" void kernel_launch(void* const* d_in, const int* in_sizes, int n_in,
                              void* d_out, int out_size) {
    const int*   node_ids = (const int*)  d_in[0];
    const int*   edge_idx = (const int*)  d_in[1];
    const float* edge_w   = (const float*)d_in[2];
    const float* emb      = (const float*)d_in[3];
    const float* W1       = (const float*)d_in[4];
    const float* b1       = (const float*)d_in[5];
    const float* W2       = (const float*)d_in[6];
    const float* b2       = (const float*)d_in[7];
    const float* gamma1   = (const float*)d_in[8];
    const float* beta1    = (const float*)d_in[9];
    const float* gamma2   = (const float*)d_in[10];
    const float* beta2    = (const float*)d_in[11];
    float* out = (float*)d_out;

    const int n = in_sizes[0];           // 50000
    const int E = in_sizes[1] / 2;       // 600000
    const int* rows = edge_idx;          // edge_index[0]
    const int* cols = edge_idx + E;      // edge_index[1]

    static bool attr_done = false;
    if (!attr_done) {
        cudaFuncSetAttribute(k_gemm, cudaFuncAttributeMaxDynamicSharedMemorySize, GEMM_SMEM);
        attr_done = true;
    }

    float *d_x, *d_h, *d_agg;
    cudaGetSymbolAddress((void**)&d_x,   g_x);
    cudaGetSymbolAddress((void**)&d_h,   g_h);
    cudaGetSymbolAddress((void**)&d_agg, g_agg);

    const int nodeBlocks = (n * 32 + 255) / 256;
    const int edgeBlocks = (E * 32 + 255) / 256;

    // degrees + inverse sqrt
    k_deg_init<<<(n + 255) / 256, 256>>>(n);
    k_deg_acc <<<(E + 255) / 256, 256>>>(cols, edge_w, E);
    k_dinv    <<<(n + 255) / 256, 256>>>(n);

    // G1 = emb @ W1
    k_small_gemm<<<VOCAB, D>>>(emb, W1);

    // ---- layer 1 ----
    k_prep1<<<nodeBlocks, 256>>>(node_ids, emb, b1, n);
    k_edge <<<edgeBlocks, 256>>>(rows, cols, edge_w, E);
    k_ln   <<<nodeBlocks, 256>>>(d_x, d_agg, gamma1, beta1, d_x, n);

    // ---- layer 2 ----
    k_gemm <<<(n + 63) / 64, 256, GEMM_SMEM>>>(d_x, W2, d_h, n);
    k_prep2<<<nodeBlocks, 256>>>(b2, n);
    k_edge <<<edgeBlocks, 256>>>(rows, cols, edge_w, E);
    k_ln   <<<nodeBlocks, 256>>>(d_x, d_agg, gamma2, beta2, out, n);
}

// round 2
// speedup vs baseline: 1.5115x; 1.5115x over previous
#include <cuda_runtime.h>

#define NN     50000
#define EE     600000
#define VOCAB  512
#define D      128
#define D4     32
#define LN_EPS 1e-5f
#define NBLK   49          // ceil(NN/1024) scan blocks

// ---------------- device scratch ----------------
__device__ __align__(16) float g_deg [NN];
__device__ __align__(16) float g_dinv[NN];
__device__ __align__(16) int   g_cnt [NN];
__device__ __align__(16) int   g_off [NN];
__device__ __align__(16) int   g_pos [NN];
__device__ __align__(16) int   g_bsum[64];
__device__ __align__(16) int   g_boff[64];
__device__ __align__(16) int2  g_adj [EE];        // (src, coef bits) CSR by dst
__device__ __align__(16) float g_x  [NN * D];
__device__ __align__(16) float g_h  [NN * D];
__device__ __align__(16) float g_G1 [VOCAB * D];

// ---------------- init: deg=1 (self loop), cnt=0 ----------------
__global__ void k_init(int n) {
    int i = blockIdx.x * blockDim.x + threadIdx.x;
    if (i < n) { g_deg[i] = 1.0f; g_cnt[i] = 0; }
}

// ---------------- per-edge: degree + histogram ----------------
__global__ void k_count(const int* __restrict__ col, const float* __restrict__ ew, int E) {
    int e = blockIdx.x * blockDim.x + threadIdx.x;
    if (e < E) {
        int c = col[e];
        atomicAdd(&g_deg[c], ew[e]);
        atomicAdd(&g_cnt[c], 1);
    }
}

// ---------------- scan stage 1: per-block exclusive scan of cnt ----------------
__global__ void k_scan1(int n) {
    __shared__ int wsum[8];
    int t = threadIdx.x, blk = blockIdx.x;
    int base = blk * 1024 + t * 4;
    int v0 = (base + 0 < n) ? g_cnt[base + 0] : 0;
    int v1 = (base + 1 < n) ? g_cnt[base + 1] : 0;
    int v2 = (base + 2 < n) ? g_cnt[base + 2] : 0;
    int v3 = (base + 3 < n) ? g_cnt[base + 3] : 0;
    int s = v0 + v1 + v2 + v3;
    int lane = t & 31, wid = t >> 5;
    int ss = s;
#pragma unroll
    for (int o = 1; o < 32; o <<= 1) {
        int u = __shfl_up_sync(0xFFFFFFFFu, ss, o);
        if (lane >= o) ss += u;
    }
    if (lane == 31) wsum[wid] = ss;
    __syncthreads();
    if (wid == 0 && lane < 8) {
        int w = wsum[lane];
#pragma unroll
        for (int o = 1; o < 8; o <<= 1) {
            int u = __shfl_up_sync(0xFFu, w, o);
            if (lane >= o) w += u;
        }
        wsum[lane] = w;
    }
    __syncthreads();
    int excl = (wid ? wsum[wid - 1] : 0) + (ss - s);
    if (base + 0 < n) g_off[base + 0] = excl;
    if (base + 1 < n) g_off[base + 1] = excl + v0;
    if (base + 2 < n) g_off[base + 2] = excl + v0 + v1;
    if (base + 3 < n) g_off[base + 3] = excl + v0 + v1 + v2;
    if (t == 0) g_bsum[blk] = wsum[7];
}

// ---------------- scan stage 2: exclusive scan of block sums (tiny) ----------------
__global__ void k_scan2() {
    if (threadIdx.x == 0) {
        int run = 0;
        for (int i = 0; i < NBLK; i++) { g_boff[i] = run; run += g_bsum[i]; }
    }
}

// ---------------- scan stage 3: add block offsets, zero pos, dinv ----------------
__global__ void k_scan3(int n) {
    int i = blockIdx.x * blockDim.x + threadIdx.x;
    if (i < n) {
        g_off[i] += g_boff[i >> 10];
        g_pos[i] = 0;
        g_dinv[i] = rsqrtf(g_deg[i]);
    }
}

// ---------------- CSR fill with precomputed coefficient ----------------
__global__ void k_fill(const int* __restrict__ rows, const int* __restrict__ cols,
                       const float* __restrict__ ew, int E) {
    int e = blockIdx.x * blockDim.x + threadIdx.x;
    if (e >= E) return;
    int r = rows[e], c = cols[e];
    float coef = g_dinv[r] * ew[e] * g_dinv[c];
    int p = atomicAdd(&g_pos[c], 1);
    g_adj[g_off[c] + p] = make_int2(r, __float_as_int(coef));
}

// ---------------- layer-1 prep: x0 = emb[nid], h1 = G1[nid] ----------------
__global__ void k_prep1(const int* __restrict__ nid, const float* __restrict__ emb, int n) {
    int gt = blockIdx.x * blockDim.x + threadIdx.x;
    int node = gt >> 5, lane = gt & 31;
    if (node >= n) return;
    int id = nid[node];
    ((float4*)g_x)[node * D4 + lane] = ((const float4*)emb )[id * D4 + lane];
    ((float4*)g_h)[node * D4 + lane] = ((const float4*)g_G1)[id * D4 + lane];
}

// ------- fused: GCN gather-aggregate + bias + residual + LayerNorm -------
__global__ void k_aggln(const float* __restrict__ h, const float* __restrict__ x,
                        const float* __restrict__ b,
                        const float* __restrict__ gamma, const float* __restrict__ beta,
                        float* __restrict__ out, int n) {
    int gt = blockIdx.x * blockDim.x + threadIdx.x;
    int node = gt >> 5, lane = gt & 31;
    if (node >= n) return;
    float di = g_dinv[node];
    float c  = di * di;
    float4 hv = ((const float4*)h)[node * D4 + lane];
    float4 bv = ((const float4*)b)[lane];
    float4 acc = make_float4(fmaf(c, hv.x, bv.x), fmaf(c, hv.y, bv.y),
                             fmaf(c, hv.z, bv.z), fmaf(c, hv.w, bv.w));
    int off = g_off[node], deg = g_cnt[node];
    const int2* __restrict__ adj = g_adj + off;
    int j = 0;
    for (; j + 1 < deg; j += 2) {
        int2 a0 = adj[j], a1 = adj[j + 1];
        float c0 = __int_as_float(a0.y), c1 = __int_as_float(a1.y);
        float4 h0 = ((const float4*)h)[a0.x * D4 + lane];
        float4 h1 = ((const float4*)h)[a1.x * D4 + lane];
        acc.x = fmaf(c0, h0.x, acc.x); acc.y = fmaf(c0, h0.y, acc.y);
        acc.z = fmaf(c0, h0.z, acc.z); acc.w = fmaf(c0, h0.w, acc.w);
        acc.x = fmaf(c1, h1.x, acc.x); acc.y = fmaf(c1, h1.y, acc.y);
        acc.z = fmaf(c1, h1.z, acc.z); acc.w = fmaf(c1, h1.w, acc.w);
    }
    if (j < deg) {
        int2 a0 = adj[j];
        float c0 = __int_as_float(a0.y);
        float4 h0 = ((const float4*)h)[a0.x * D4 + lane];
        acc.x = fmaf(c0, h0.x, acc.x); acc.y = fmaf(c0, h0.y, acc.y);
        acc.z = fmaf(c0, h0.z, acc.z); acc.w = fmaf(c0, h0.w, acc.w);
    }
    // residual
    float4 xv = ((const float4*)x)[node * D4 + lane];
    acc.x += xv.x; acc.y += xv.y; acc.z += xv.z; acc.w += xv.w;
    // LayerNorm (warp reduce)
    float s  = acc.x + acc.y + acc.z + acc.w;
    float sq = acc.x * acc.x + acc.y * acc.y + acc.z * acc.z + acc.w * acc.w;
#pragma unroll
    for (int o = 16; o > 0; o >>= 1) {
        s  += __shfl_xor_sync(0xFFFFFFFFu, s,  o);
        sq += __shfl_xor_sync(0xFFFFFFFFu, sq, o);
    }
    float mu  = s * (1.f / D);
    float var = sq * (1.f / D) - mu * mu;
    float rs  = rsqrtf(var + LN_EPS);
    float4 g  = ((const float4*)gamma)[lane];
    float4 be = ((const float4*)beta )[lane];
    float4 o;
    o.x = (acc.x - mu) * rs * g.x + be.x;
    o.y = (acc.y - mu) * rs * g.y + be.y;
    o.z = (acc.z - mu) * rs * g.z + be.z;
    o.w = (acc.w - mu) * rs * g.w + be.w;
    ((float4*)out)[node * D4 + lane] = o;
}

// ---------------- GEMM: H = X @ W with packed fma.rn.f32x2 ----------------
typedef unsigned long long ull;

__device__ __forceinline__ ull pk2(float a) {
    ull r; asm("mov.b64 %0, {%1, %1};" : "=l"(r) : "f"(a)); return r;
}
__device__ __forceinline__ void fma2(ull& d, ull a, ull b) {
    asm("fma.rn.f32x2 %0, %1, %2, %0;" : "+l"(d) : "l"(a), "l"(b));
}

#define XS_PITCH 136   // floats; 136*4 = 544 B, 16B aligned, avoids conflicts
#define GEMM_SMEM (64 * XS_PITCH * 4 + 128 * 128 * 4)

__global__ void __launch_bounds__(256) k_gemm(const float* __restrict__ X,
                                              const float* __restrict__ W,
                                              float* __restrict__ H, int n) {
    extern __shared__ float smem[];
    float* Xs = smem;                    // [64][XS_PITCH]
    float* Ws = smem + 64 * XS_PITCH;    // [128][128]

    int t  = threadIdx.x;
    int m0 = blockIdx.x * 64;

    const float4* W4  = (const float4*)W;
    float4*       Ws4 = (float4*)Ws;
#pragma unroll
    for (int i = 0; i < 16; i++) Ws4[t + i * 256] = W4[t + i * 256];

#pragma unroll
    for (int i = 0; i < 8; i++) {
        int idx = t + i * 256;
        int r = idx >> 5, kc = idx & 31;
        float4 v = make_float4(0.f, 0.f, 0.f, 0.f);
        if (m0 + r < n) v = ((const float4*)X)[(m0 + r) * D4 + kc];
        *(float4*)&Xs[r * XS_PITCH + kc * 4] = v;
    }
    __syncthreads();

    int cg = t & 15;   // col group: cols [cg*4, cg*4+3] and [64+cg*4, ...]
    int rg = t >> 4;   // row group: rows rg*4 .. rg*4+3

    ull acc[4][4];
#pragma unroll
    for (int i = 0; i < 4; i++)
#pragma unroll
        for (int j = 0; j < 4; j++) acc[i][j] = 0ull;

#pragma unroll 2
    for (int k0 = 0; k0 < D; k0 += 4) {
        float4 A[4];
#pragma unroll
        for (int i = 0; i < 4; i++)
            A[i] = *(const float4*)&Xs[(rg * 4 + i) * XS_PITCH + k0];
#pragma unroll
        for (int kk = 0; kk < 4; kk++) {
            ulonglong2 w0 = *(const ulonglong2*)&Ws[(k0 + kk) * D + cg * 4];
            ulonglong2 w1 = *(const ulonglong2*)&Ws[(k0 + kk) * D + 64 + cg * 4];
#pragma unroll
            for (int i = 0; i < 4; i++) {
                float av = (kk == 0) ? A[i].x : (kk == 1) ? A[i].y
                         : (kk == 2) ? A[i].z : A[i].w;
                ull ap = pk2(av);
                fma2(acc[i][0], ap, w0.x);
                fma2(acc[i][1], ap, w0.y);
                fma2(acc[i][2], ap, w1.x);
                fma2(acc[i][3], ap, w1.y);
            }
        }
    }

    union Cv { ull u; float2 f; };
#pragma unroll
    for (int i = 0; i < 4; i++) {
        int row = m0 + rg * 4 + i;
        if (row < n) {
            Cv c0, c1, c2, c3;
            c0.u = acc[i][0]; c1.u = acc[i][1]; c2.u = acc[i][2]; c3.u = acc[i][3];
            ((float4*)H)[row * D4 + cg]      = make_float4(c0.f.x, c0.f.y, c1.f.x, c1.f.y);
            ((float4*)H)[row * D4 + 16 + cg] = make_float4(c2.f.x, c2.f.y, c3.f.x, c3.f.y);
        }
    }
}

// ---------------- host launch ----------------
extern "C" void kernel_launch(void* const* d_in, const int* in_sizes, int n_in,
                              void* d_out, int out_size) {
    const int*   node_ids = (const int*)  d_in[0];
    const int*   edge_idx = (const int*)  d_in[1];
    const float* edge_w   = (const float*)d_in[2];
    const float* emb      = (const float*)d_in[3];
    const float* W1       = (const float*)d_in[4];
    const float* b1       = (const float*)d_in[5];
    const float* W2       = (const float*)d_in[6];
    const float* b2       = (const float*)d_in[7];
    const float* gamma1   = (const float*)d_in[8];
    const float* beta1    = (const float*)d_in[9];
    const float* gamma2   = (const float*)d_in[10];
    const float* beta2    = (const float*)d_in[11];
    float* out = (float*)d_out;

    const int n = in_sizes[0];
    const int E = in_sizes[1] / 2;
    const int* rows = edge_idx;
    const int* cols = edge_idx + E;

    static bool attr_done = false;
    if (!attr_done) {
        cudaFuncSetAttribute(k_gemm, cudaFuncAttributeMaxDynamicSharedMemorySize, GEMM_SMEM);
        attr_done = true;
    }

    float *d_x, *d_h, *d_G1;
    cudaGetSymbolAddress((void**)&d_x,  g_x);
    cudaGetSymbolAddress((void**)&d_h,  g_h);
    cudaGetSymbolAddress((void**)&d_G1, g_G1);

    const int nodeBlocks = (n * 32 + 255) / 256;

    // CSR build + degree norm
    k_init <<<(n + 255) / 256, 256>>>(n);
    k_count<<<(E + 255) / 256, 256>>>(cols, edge_w, E);
    k_scan1<<<NBLK, 256>>>(n);
    k_scan2<<<1, 32>>>();
    k_scan3<<<(n + 255) / 256, 256>>>(n);
    k_fill <<<(E + 255) / 256, 256>>>(rows, cols, edge_w, E);

    // G1 = emb @ W1 (512 rows through the main GEMM)
    k_gemm <<<(VOCAB + 63) / 64, 256, GEMM_SMEM>>>(emb, W1, d_G1, VOCAB);

    // layer 1
    k_prep1<<<nodeBlocks, 256>>>(node_ids, emb, n);
    k_aggln<<<nodeBlocks, 256>>>(d_h, d_x, b1, gamma1, beta1, d_x, n);

    // layer 2
    k_gemm <<<(n + 63) / 64, 256, GEMM_SMEM>>>(d_x, W2, d_h, n);
    k_aggln<<<nodeBlocks, 256>>>(d_h, d_x, b2, gamma2, beta2, out, n);
}

// round 3
// speedup vs baseline: 1.5680x; 1.0374x over previous
#include <cuda_runtime.h>

#define NN     50000
#define EE     600000
#define VOCAB  512
#define D      128
#define D4     32
#define LN_EPS 1e-5f
#define NBLK   49          // ceil(NN/1024) scan blocks

// ---------------- device scratch ----------------
__device__ __align__(16) float g_deg [NN];
__device__ __align__(16) float g_dinv[NN];
__device__ __align__(16) int   g_cnt [NN];
__device__ __align__(16) int   g_off [NN];
__device__ __align__(16) int   g_pos [NN];
__device__ __align__(16) int   g_bsum[64];
__device__ __align__(16) int   g_boff[64];
__device__ __align__(16) int2  g_adj [EE];        // (src node, coef) CSR by dst
__device__ __align__(16) int2  g_adj1[EE];        // (vocab id,  coef) CSR by dst
__device__ __align__(16) float g_x  [NN * D];
__device__ __align__(16) float g_h  [NN * D];
__device__ __align__(16) float g_G1 [VOCAB * D];  // emb @ W1

// ---------------- init ----------------
__global__ void k_init(int n) {
    int i = blockIdx.x * blockDim.x + threadIdx.x;
    if (i < n) { g_deg[i] = 1.0f; g_cnt[i] = 0; }
}

// ---------------- per-edge: degree + histogram ----------------
__global__ void k_count(const int* __restrict__ col, const float* __restrict__ ew, int E) {
    int e = blockIdx.x * blockDim.x + threadIdx.x;
    if (e < E) {
        int c = col[e];
        atomicAdd(&g_deg[c], ew[e]);
        atomicAdd(&g_cnt[c], 1);
    }
}

// ---------------- scan stage 1: per-block exclusive scan of cnt ----------------
__global__ void k_scan1(int n) {
    __shared__ int wsum[8];
    int t = threadIdx.x, blk = blockIdx.x;
    int base = blk * 1024 + t * 4;
    int v0 = (base + 0 < n) ? g_cnt[base + 0] : 0;
    int v1 = (base + 1 < n) ? g_cnt[base + 1] : 0;
    int v2 = (base + 2 < n) ? g_cnt[base + 2] : 0;
    int v3 = (base + 3 < n) ? g_cnt[base + 3] : 0;
    int s = v0 + v1 + v2 + v3;
    int lane = t & 31, wid = t >> 5;
    int ss = s;
#pragma unroll
    for (int o = 1; o < 32; o <<= 1) {
        int u = __shfl_up_sync(0xFFFFFFFFu, ss, o);
        if (lane >= o) ss += u;
    }
    if (lane == 31) wsum[wid] = ss;
    __syncthreads();
    if (wid == 0 && lane < 8) {
        int w = wsum[lane];
#pragma unroll
        for (int o = 1; o < 8; o <<= 1) {
            int u = __shfl_up_sync(0xFFu, w, o);
            if (lane >= o) w += u;
        }
        wsum[lane] = w;
    }
    __syncthreads();
    int excl = (wid ? wsum[wid - 1] : 0) + (ss - s);
    if (base + 0 < n) g_off[base + 0] = excl;
    if (base + 1 < n) g_off[base + 1] = excl + v0;
    if (base + 2 < n) g_off[base + 2] = excl + v0 + v1;
    if (base + 3 < n) g_off[base + 3] = excl + v0 + v1 + v2;
    if (t == 0) g_bsum[blk] = wsum[7];
}

// ---------------- scan stage 2: warp-parallel scan of block sums ----------------
__global__ void k_scan2() {
    int t = threadIdx.x;                         // one warp
    int v0 = (t < NBLK) ? g_bsum[t] : 0;
    int s0 = v0;
#pragma unroll
    for (int o = 1; o < 32; o <<= 1) {
        int u = __shfl_up_sync(0xFFFFFFFFu, s0, o);
        if (t >= o) s0 += u;
    }
    if (t < NBLK) g_boff[t] = s0 - v0;
    int tot = __shfl_sync(0xFFFFFFFFu, s0, 31);
    int i1 = 32 + t;
    int v1 = (i1 < NBLK) ? g_bsum[i1] : 0;
    int s1 = v1;
#pragma unroll
    for (int o = 1; o < 32; o <<= 1) {
        int u = __shfl_up_sync(0xFFFFFFFFu, s1, o);
        if (t >= o) s1 += u;
    }
    if (i1 < NBLK) g_boff[i1] = tot + s1 - v1;
}

// ---------------- scan stage 3: add block offsets, zero pos, dinv ----------------
__global__ void k_scan3(int n) {
    int i = blockIdx.x * blockDim.x + threadIdx.x;
    if (i < n) {
        g_off[i] += g_boff[i >> 10];
        g_pos[i] = 0;
        g_dinv[i] = rsqrtf(g_deg[i]);
    }
}

// ---------------- CSR fill: both (src, coef) and (vocab_id, coef) ----------------
__global__ void k_fill(const int* __restrict__ rows, const int* __restrict__ cols,
                       const float* __restrict__ ew, const int* __restrict__ nid, int E) {
    int e = blockIdx.x * blockDim.x + threadIdx.x;
    if (e >= E) return;
    int r = rows[e], c = cols[e];
    float coef = g_dinv[r] * ew[e] * g_dinv[c];
    int p = g_off[c] + atomicAdd(&g_pos[c], 1);
    int cb = __float_as_int(coef);
    g_adj [p] = make_int2(r, cb);
    g_adj1[p] = make_int2(nid[r], cb);
}

// ------- layer 1 fused: aggregate from 512-row G1 table + bias + residual(emb) + LN ----
__global__ void k_agg1(const int* __restrict__ nid, const float* __restrict__ emb,
                       const float* __restrict__ b,
                       const float* __restrict__ gamma, const float* __restrict__ beta,
                       float* __restrict__ out, int n) {
    int gt = blockIdx.x * blockDim.x + threadIdx.x;
    int node = gt >> 5, lane = gt & 31;
    if (node >= n) return;
    int id = nid[node];
    float di = g_dinv[node];
    float c  = di * di;
    float4 hv = ((const float4*)g_G1)[id * D4 + lane];     // self h (L1-hot)
    float4 bv = ((const float4*)b)[lane];
    float4 acc = make_float4(fmaf(c, hv.x, bv.x), fmaf(c, hv.y, bv.y),
                             fmaf(c, hv.z, bv.z), fmaf(c, hv.w, bv.w));
    int off = g_off[node], deg = g_cnt[node];
    const int2* __restrict__ adj = g_adj1 + off;
    int j = 0;
    for (; j + 3 < deg; j += 4) {
        int2 a0 = adj[j], a1 = adj[j+1], a2 = adj[j+2], a3 = adj[j+3];
        float4 h0 = ((const float4*)g_G1)[a0.x * D4 + lane];
        float4 h1 = ((const float4*)g_G1)[a1.x * D4 + lane];
        float4 h2 = ((const float4*)g_G1)[a2.x * D4 + lane];
        float4 h3 = ((const float4*)g_G1)[a3.x * D4 + lane];
        float c0 = __int_as_float(a0.y), c1 = __int_as_float(a1.y);
        float c2 = __int_as_float(a2.y), c3 = __int_as_float(a3.y);
        acc.x = fmaf(c0,h0.x,acc.x); acc.y = fmaf(c0,h0.y,acc.y); acc.z = fmaf(c0,h0.z,acc.z); acc.w = fmaf(c0,h0.w,acc.w);
        acc.x = fmaf(c1,h1.x,acc.x); acc.y = fmaf(c1,h1.y,acc.y); acc.z = fmaf(c1,h1.z,acc.z); acc.w = fmaf(c1,h1.w,acc.w);
        acc.x = fmaf(c2,h2.x,acc.x); acc.y = fmaf(c2,h2.y,acc.y); acc.z = fmaf(c2,h2.z,acc.z); acc.w = fmaf(c2,h2.w,acc.w);
        acc.x = fmaf(c3,h3.x,acc.x); acc.y = fmaf(c3,h3.y,acc.y); acc.z = fmaf(c3,h3.z,acc.z); acc.w = fmaf(c3,h3.w,acc.w);
    }
    for (; j < deg; j++) {
        int2 a0 = adj[j];
        float c0 = __int_as_float(a0.y);
        float4 h0 = ((const float4*)g_G1)[a0.x * D4 + lane];
        acc.x = fmaf(c0,h0.x,acc.x); acc.y = fmaf(c0,h0.y,acc.y); acc.z = fmaf(c0,h0.z,acc.z); acc.w = fmaf(c0,h0.w,acc.w);
    }
    float4 xv = ((const float4*)emb)[id * D4 + lane];      // residual (L1-hot)
    acc.x += xv.x; acc.y += xv.y; acc.z += xv.z; acc.w += xv.w;
    float s  = acc.x + acc.y + acc.z + acc.w;
    float sq = acc.x*acc.x + acc.y*acc.y + acc.z*acc.z + acc.w*acc.w;
#pragma unroll
    for (int o = 16; o > 0; o >>= 1) {
        s  += __shfl_xor_sync(0xFFFFFFFFu, s,  o);
        sq += __shfl_xor_sync(0xFFFFFFFFu, sq, o);
    }
    float mu  = s * (1.f / D);
    float var = sq * (1.f / D) - mu * mu;
    float rs  = rsqrtf(var + LN_EPS);
    float4 g  = ((const float4*)gamma)[lane];
    float4 be = ((const float4*)beta )[lane];
    float4 o;
    o.x = (acc.x - mu) * rs * g.x + be.x;
    o.y = (acc.y - mu) * rs * g.y + be.y;
    o.z = (acc.z - mu) * rs * g.z + be.z;
    o.w = (acc.w - mu) * rs * g.w + be.w;
    ((float4*)out)[node * D4 + lane] = o;
}

// ------- layer 2 fused: gather-aggregate from h + bias + residual + LN -------
__global__ void k_agg2(const float* __restrict__ h, const float* __restrict__ x,
                       const float* __restrict__ b,
                       const float* __restrict__ gamma, const float* __restrict__ beta,
                       float* __restrict__ out, int n) {
    int gt = blockIdx.x * blockDim.x + threadIdx.x;
    int node = gt >> 5, lane = gt & 31;
    if (node >= n) return;
    float di = g_dinv[node];
    float c  = di * di;
    float4 hv = ((const float4*)h)[node * D4 + lane];
    float4 bv = ((const float4*)b)[lane];
    float4 acc = make_float4(fmaf(c, hv.x, bv.x), fmaf(c, hv.y, bv.y),
                             fmaf(c, hv.z, bv.z), fmaf(c, hv.w, bv.w));
    int off = g_off[node], deg = g_cnt[node];
    const int2* __restrict__ adj = g_adj + off;
    int j = 0;
    for (; j + 3 < deg; j += 4) {
        int2 a0 = adj[j], a1 = adj[j+1], a2 = adj[j+2], a3 = adj[j+3];
        float4 h0 = ((const float4*)h)[a0.x * D4 + lane];
        float4 h1 = ((const float4*)h)[a1.x * D4 + lane];
        float4 h2 = ((const float4*)h)[a2.x * D4 + lane];
        float4 h3 = ((const float4*)h)[a3.x * D4 + lane];
        float c0 = __int_as_float(a0.y), c1 = __int_as_float(a1.y);
        float c2 = __int_as_float(a2.y), c3 = __int_as_float(a3.y);
        acc.x = fmaf(c0,h0.x,acc.x); acc.y = fmaf(c0,h0.y,acc.y); acc.z = fmaf(c0,h0.z,acc.z); acc.w = fmaf(c0,h0.w,acc.w);
        acc.x = fmaf(c1,h1.x,acc.x); acc.y = fmaf(c1,h1.y,acc.y); acc.z = fmaf(c1,h1.z,acc.z); acc.w = fmaf(c1,h1.w,acc.w);
        acc.x = fmaf(c2,h2.x,acc.x); acc.y = fmaf(c2,h2.y,acc.y); acc.z = fmaf(c2,h2.z,acc.z); acc.w = fmaf(c2,h2.w,acc.w);
        acc.x = fmaf(c3,h3.x,acc.x); acc.y = fmaf(c3,h3.y,acc.y); acc.z = fmaf(c3,h3.z,acc.z); acc.w = fmaf(c3,h3.w,acc.w);
    }
    for (; j < deg; j++) {
        int2 a0 = adj[j];
        float c0 = __int_as_float(a0.y);
        float4 h0 = ((const float4*)h)[a0.x * D4 + lane];
        acc.x = fmaf(c0,h0.x,acc.x); acc.y = fmaf(c0,h0.y,acc.y); acc.z = fmaf(c0,h0.z,acc.z); acc.w = fmaf(c0,h0.w,acc.w);
    }
    float4 xv = ((const float4*)x)[node * D4 + lane];
    acc.x += xv.x; acc.y += xv.y; acc.z += xv.z; acc.w += xv.w;
    float s  = acc.x + acc.y + acc.z + acc.w;
    float sq = acc.x*acc.x + acc.y*acc.y + acc.z*acc.z + acc.w*acc.w;
#pragma unroll
    for (int o = 16; o > 0; o >>= 1) {
        s  += __shfl_xor_sync(0xFFFFFFFFu, s,  o);
        sq += __shfl_xor_sync(0xFFFFFFFFu, sq, o);
    }
    float mu  = s * (1.f / D);
    float var = sq * (1.f / D) - mu * mu;
    float rs  = rsqrtf(var + LN_EPS);
    float4 g  = ((const float4*)gamma)[lane];
    float4 be = ((const float4*)beta )[lane];
    float4 o;
    o.x = (acc.x - mu) * rs * g.x + be.x;
    o.y = (acc.y - mu) * rs * g.y + be.y;
    o.z = (acc.z - mu) * rs * g.z + be.z;
    o.w = (acc.w - mu) * rs * g.w + be.w;
    ((float4*)out)[node * D4 + lane] = o;
}

// ---------------- GEMM: H = X @ W with packed fma.rn.f32x2 ----------------
typedef unsigned long long ull;

__device__ __forceinline__ ull pk2(float a) {
    ull r; asm("mov.b64 %0, {%1, %1};" : "=l"(r) : "f"(a)); return r;
}
__device__ __forceinline__ void fma2(ull& d, ull a, ull b) {
    asm("fma.rn.f32x2 %0, %1, %2, %0;" : "+l"(d) : "l"(a), "l"(b));
}

#define XS_PITCH 136
#define GEMM_SMEM (64 * XS_PITCH * 4 + 128 * 128 * 4)

__global__ void __launch_bounds__(256) k_gemm(const float* __restrict__ X,
                                              const float* __restrict__ W,
                                              float* __restrict__ H, int n) {
    extern __shared__ float smem[];
    float* Xs = smem;                    // [64][XS_PITCH]
    float* Ws = smem + 64 * XS_PITCH;    // [128][128]

    int t  = threadIdx.x;
    int m0 = blockIdx.x * 64;

    const float4* W4  = (const float4*)W;
    float4*       Ws4 = (float4*)Ws;
#pragma unroll
    for (int i = 0; i < 16; i++) Ws4[t + i * 256] = W4[t + i * 256];

#pragma unroll
    for (int i = 0; i < 8; i++) {
        int idx = t + i * 256;
        int r = idx >> 5, kc = idx & 31;
        float4 v = make_float4(0.f, 0.f, 0.f, 0.f);
        if (m0 + r < n) v = ((const float4*)X)[(m0 + r) * D4 + kc];
        *(float4*)&Xs[r * XS_PITCH + kc * 4] = v;
    }
    __syncthreads();

    int cg = t & 15;
    int rg = t >> 4;

    ull acc[4][4];
#pragma unroll
    for (int i = 0; i < 4; i++)
#pragma unroll
        for (int j = 0; j < 4; j++) acc[i][j] = 0ull;

#pragma unroll 2
    for (int k0 = 0; k0 < D; k0 += 4) {
        float4 A[4];
#pragma unroll
        for (int i = 0; i < 4; i++)
            A[i] = *(const float4*)&Xs[(rg * 4 + i) * XS_PITCH + k0];
#pragma unroll
        for (int kk = 0; kk < 4; kk++) {
            ulonglong2 w0 = *(const ulonglong2*)&Ws[(k0 + kk) * D + cg * 4];
            ulonglong2 w1 = *(const ulonglong2*)&Ws[(k0 + kk) * D + 64 + cg * 4];
#pragma unroll
            for (int i = 0; i < 4; i++) {
                float av = (kk == 0) ? A[i].x : (kk == 1) ? A[i].y
                         : (kk == 2) ? A[i].z : A[i].w;
                ull ap = pk2(av);
                fma2(acc[i][0], ap, w0.x);
                fma2(acc[i][1], ap, w0.y);
                fma2(acc[i][2], ap, w1.x);
                fma2(acc[i][3], ap, w1.y);
            }
        }
    }

    union Cv { ull u; float2 f; };
#pragma unroll
    for (int i = 0; i < 4; i++) {
        int row = m0 + rg * 4 + i;
        if (row < n) {
            Cv c0, c1, c2, c3;
            c0.u = acc[i][0]; c1.u = acc[i][1]; c2.u = acc[i][2]; c3.u = acc[i][3];
            ((float4*)H)[row * D4 + cg]      = make_float4(c0.f.x, c0.f.y, c1.f.x, c1.f.y);
            ((float4*)H)[row * D4 + 16 + cg] = make_float4(c2.f.x, c2.f.y, c3.f.x, c3.f.y);
        }
    }
}

// ---------------- host launch ----------------
extern "C" void kernel_launch(void* const* d_in, const int* in_sizes, int n_in,
                              void* d_out, int out_size) {
    const int*   node_ids = (const int*)  d_in[0];
    const int*   edge_idx = (const int*)  d_in[1];
    const float* edge_w   = (const float*)d_in[2];
    const float* emb      = (const float*)d_in[3];
    const float* W1       = (const float*)d_in[4];
    const float* b1       = (const float*)d_in[5];
    const float* W2       = (const float*)d_in[6];
    const float* b2       = (const float*)d_in[7];
    const float* gamma1   = (const float*)d_in[8];
    const float* beta1    = (const float*)d_in[9];
    const float* gamma2   = (const float*)d_in[10];
    const float* beta2    = (const float*)d_in[11];
    float* out = (float*)d_out;

    const int n = in_sizes[0];
    const int E = in_sizes[1] / 2;
    const int* rows = edge_idx;
    const int* cols = edge_idx + E;

    static bool attr_done = false;
    if (!attr_done) {
        cudaFuncSetAttribute(k_gemm, cudaFuncAttributeMaxDynamicSharedMemorySize, GEMM_SMEM);
        attr_done = true;
    }

    float *d_x, *d_h, *d_G1;
    cudaGetSymbolAddress((void**)&d_x,  g_x);
    cudaGetSymbolAddress((void**)&d_h,  g_h);
    cudaGetSymbolAddress((void**)&d_G1, g_G1);

    const int nodeBlocks = (n * 32 + 255) / 256;

    // CSR build + degree norm
    k_init <<<(n + 255) / 256, 256>>>(n);
    k_count<<<(E + 255) / 256, 256>>>(cols, edge_w, E);
    k_scan1<<<NBLK, 256>>>(n);
    k_scan2<<<1, 32>>>();
    k_scan3<<<(n + 255) / 256, 256>>>(n);
    k_fill <<<(E + 255) / 256, 256>>>(rows, cols, edge_w, node_ids, E);

    // G1 = emb @ W1
    k_gemm <<<(VOCAB + 63) / 64, 256, GEMM_SMEM>>>(emb, W1, d_G1, VOCAB);

    // layer 1 (fully fused: gather from G1/emb tables)
    k_agg1 <<<nodeBlocks, 256>>>(node_ids, emb, b1, gamma1, beta1, d_x, n);

    // layer 2
    k_gemm <<<(n + 63) / 64, 256, GEMM_SMEM>>>(d_x, W2, d_h, n);
    k_agg2 <<<nodeBlocks, 256>>>(d_h, d_x, b2, gamma2, beta2, out, n);
}